// round 10
// baseline (speedup 1.0000x reference)
#include <cuda_runtime.h>
#include <cstdint>

// Problem shape (fixed by the reference setup_inputs)
#define B_SZ   4
#define N_PTS  8192
#define M_PTS  8192

// Chamfer compute tiling (R5 config: best measured)
#define BLOCK  128                 // threads per block (4 warps)
#define OWN    8                   // owner pred points per thread
#define TI     (BLOCK * OWN)       // 1024 pred points per block
#define TILE   256                 // target points per block (one shared tile)
#define TILE2  (TILE / 2)          // packed j-pairs
#define IC     (N_PTS / TI)        // 8  i-chunks
#define JC     (M_PTS / TILE)      // 32 j-chunks
#define NPTS_T (B_SZ * N_PTS)      // 32768 (== B_SZ * M_PTS)

#define FINF __int_as_float(0x7f800000)

typedef unsigned long long ull;

// Complement-encoded global min arrays. v = 0.5*d^2 >= 0 always, so
// enc(v) = ~bits(v) is monotone DECREASING in v => max(enc) == min(v),
// with identity 0 (the zero-init / reset state). Folded via atomicMax
// with unused return => REDG (fire-and-forget).
__device__ unsigned gEncX[NPTS_T];   // min_j 0.5*d^2 per pred point (encoded)
__device__ unsigned gEncY[NPTS_T];   // min_i 0.5*d^2 per target point (encoded)
__device__ float gSumX;
__device__ float gSumY;
__device__ int   gCount;

__device__ __forceinline__ unsigned encMin(float v) {
    return ~__float_as_uint(v);
}
__device__ __forceinline__ float decMin(unsigned e) {
    return __uint_as_float(~e);
}

// ---- packed f32x2 helpers ----
__device__ __forceinline__ ull pack2(float lo, float hi) {
    ull r;
    asm("mov.b64 %0, {%1,%2};" : "=l"(r) : "f"(lo), "f"(hi));
    return r;
}
__device__ __forceinline__ ull fma2(ull a, ull b, ull c) {
    ull d;
    asm("fma.rn.f32x2 %0, %1, %2, %3;" : "=l"(d) : "l"(a), "l"(b), "l"(c));
    return d;
}
__device__ __forceinline__ ull add2(ull a, ull b) {
    ull d;
    asm("add.rn.f32x2 %0, %1, %2;" : "=l"(d) : "l"(a), "l"(b));
    return d;
}
__device__ __forceinline__ void unpack2(ull v, float& lo, float& hi) {
    asm("mov.b64 {%0,%1}, %2;" : "=f"(lo), "=f"(hi) : "l"(v));
}

// Each unique pair (i,j) computed exactly ONCE as v = 0.5*d^2(i,j)  (R5 loop).
// Row mins -> register accumulators -> REDG encoded fold.
// Col mins -> per-warp shared arrays (lane-rotated, race-free) -> REDG fold.
__global__ __launch_bounds__(BLOCK) void chamfer_kernel(
    const float* __restrict__ pred, const float* __restrict__ target)
{
    // Pair-packed SoA target tile: element k holds coords of {j=2k, j=2k+1}.
    __shared__ ull sTx[TILE2], sTy[TILE2], sTz[TILE2], sTw[TILE2];
    __shared__ ull sCol[BLOCK / 32][TILE2];   // per-warp packed column mins

    const int b = blockIdx.z;
    const float* __restrict__ predB = pred   + (size_t)b * N_PTS * 3;
    const float* __restrict__ targB = target + (size_t)b * M_PTS * 3;

    const int ic = blockIdx.x;
    const int jc = blockIdx.y;
    const int Ibase = ic * TI;
    const int Jbase = jc * TILE;
    const int t = threadIdx.x;
    const int lane = t & 31;
    const int w = t >> 5;

    // init per-warp colmins to +inf
    ull inf2 = pack2(FINF, FINF);
#pragma unroll
    for (int k = t; k < (BLOCK / 32) * TILE2; k += BLOCK)
        ((ull*)sCol)[k] = inf2;

    // load target tile (x, y, z, 0.5|t|^2), pair-packed SoA
    for (int k = t; k < TILE; k += BLOCK) {
        int j = Jbase + k;
        float x = targB[3 * j + 0], y = targB[3 * j + 1], z = targB[3 * j + 2];
        ((float*)sTx)[k] = x;
        ((float*)sTy)[k] = y;
        ((float*)sTz)[k] = z;
        ((float*)sTw)[k] = 0.5f * (x * x + y * y + z * z);
    }

    // owner pred points: negated coords + half-norm, duplicated into f32x2 pairs
    ull ax[OWN], ay[OWN], az[OWN], hp[OWN];
    float rm[OWN];
#pragma unroll
    for (int p = 0; p < OWN; p++) {
        int i = Ibase + t + p * BLOCK;
        float x = predB[3 * i + 0], y = predB[3 * i + 1], z = predB[3 * i + 2];
        float h = 0.5f * (x * x + y * y + z * z);
        ax[p] = pack2(-x, -x); ay[p] = pack2(-y, -y); az[p] = pack2(-z, -z);
        hp[p] = pack2(h, h);
        rm[p] = FINF;
    }

    __syncthreads();

    ull* scol = sCol[w];

    for (int s = 0; s < TILE2; s++) {
        int jp = (s + lane) & (TILE2 - 1);   // lane-exclusive within warp each step
        ull tx = sTx[jp], ty = sTy[jp], tz = sTz[jp], tw = sTw[jp];
        float c0 = FINF, c1 = FINF;
#pragma unroll
        for (int p = 0; p < OWN; p++) {
            ull v = fma2(az[p], tz, add2(tw, hp[p]));  // 0.5(|p|^2+|t|^2) - pz*tz
            v = fma2(ay[p], ty, v);
            v = fma2(ax[p], tx, v);                     // = 0.5 * d^2  (>= 0)
            float v0, v1;
            unpack2(v, v0, v1);
            rm[p] = fminf(rm[p], fminf(v0, v1));        // row min (over j)
            c0 = fminf(c0, v0);                          // col partial
            c1 = fminf(c1, v1);
        }
        // fold into per-warp column min (lane-exclusive jp, no race)
        ull cc = scol[jp];
        float o0, o1;
        unpack2(cc, o0, o1);
        scol[jp] = pack2(fminf(o0, c0), fminf(o1, c1));
    }

    // row mins -> global encoded fold (return unused => REDG)
#pragma unroll
    for (int p = 0; p < OWN; p++)
        atomicMax(&gEncX[b * N_PTS + Ibase + t + p * BLOCK], encMin(rm[p]));

    __syncthreads();

    // column mins: combine 4 warps' arrays, one jp per thread (BLOCK == TILE2)
    {
        int jp = t;
        float m0 = FINF, m1 = FINF;
#pragma unroll
        for (int w2 = 0; w2 < BLOCK / 32; w2++) {
            float a, bb;
            unpack2(sCol[w2][jp], a, bb);
            m0 = fminf(m0, a);
            m1 = fminf(m1, bb);
        }
        atomicMax(&gEncY[b * M_PTS + Jbase + 2 * jp + 0], encMin(m0));
        atomicMax(&gEncY[b * M_PTS + Jbase + 2 * jp + 1], encMin(m1));
    }

    // PDL: make this CTA's REDs visible, then allow dependents to schedule.
    __threadfence();
    asm volatile("griddepcontrol.launch_dependents;");
}

// Global sum of 2*min values + finalize + reset-for-next-replay.
// Launched with programmatic stream serialization: prelude overlaps chamfer.
__global__ __launch_bounds__(256) void reduce_fin_kernel(
    const float* __restrict__ bpp, const float* __restrict__ lamda,
    float* __restrict__ out)
{
    __shared__ float sx[256 / 32];
    __shared__ float sy[256 / 32];

    const int i    = blockIdx.x * blockDim.x + threadIdx.x;
    const int lane = threadIdx.x & 31;
    const int warp = threadIdx.x >> 5;

    // Wait until the chamfer grid's memory is visible.
    asm volatile("griddepcontrol.wait;" ::: "memory");

    float vx = 2.0f * decMin(gEncX[i]);   // d^2 = 2 * (0.5 d^2)
    float vy = 2.0f * decMin(gEncY[i]);

    // reset for the next graph replay (identity of the encoded max is 0)
    gEncX[i] = 0u;
    gEncY[i] = 0u;

#pragma unroll
    for (int off = 16; off > 0; off >>= 1) {
        vx += __shfl_down_sync(0xffffffffu, vx, off);
        vy += __shfl_down_sync(0xffffffffu, vy, off);
    }
    if (lane == 0) { sx[warp] = vx; sy[warp] = vy; }
    __syncthreads();
    if (warp == 0) {
        vx = (lane < (256 >> 5)) ? sx[lane] : 0.0f;
        vy = (lane < (256 >> 5)) ? sy[lane] : 0.0f;
#pragma unroll
        for (int off = 4; off > 0; off >>= 1) {
            vx += __shfl_down_sync(0xffffffffu, vx, off);
            vy += __shfl_down_sync(0xffffffffu, vy, off);
        }
        if (lane == 0) {
            atomicAdd(&gSumX, vx);
            atomicAdd(&gSumY, vy);
            __threadfence();
            int ticket = atomicAdd(&gCount, 1);
            if (ticket == (int)gridDim.x - 1) {
                float sX = atomicAdd(&gSumX, 0.0f);   // all prior adds visible
                float sY = atomicAdd(&gSumY, 0.0f);
                float dist = sX * (1.0f / (B_SZ * N_PTS)) + sY * (1.0f / (B_SZ * M_PTS));
                out[0] = dist + lamda[0] * bpp[0];
                // reset accumulators for the next graph replay
                gSumX = 0.0f;
                gSumY = 0.0f;
                __threadfence();
                gCount = 0;
            }
        }
    }
}

extern "C" void kernel_launch(void* const* d_in, const int* in_sizes, int n_in,
                              void* d_out, int out_size)
{
    const float* pred   = (const float*)d_in[0];
    const float* target = (const float*)d_in[1];
    const float* bpp    = (const float*)d_in[2];
    const float* lamda  = (const float*)d_in[3];
    float* out = (float*)d_out;

    // 1) single-pass chamfer: each pair once as 0.5*d^2; mins folded into
    //    zero-identity encoded arrays via REDG (no init kernel, no partials)
    dim3 grid(IC, JC, B_SZ);   // (8, 32, 4) = 1024 blocks
    chamfer_kernel<<<grid, BLOCK>>>(pred, target);

    // 2) reduce+finalize, launched with PDL so its setup overlaps the chamfer tail
    {
        cudaLaunchConfig_t cfg = {};
        cfg.gridDim  = dim3(NPTS_T / 256, 1, 1);
        cfg.blockDim = dim3(256, 1, 1);
        cfg.dynamicSmemBytes = 0;
        cudaLaunchAttribute attrs[1];
        attrs[0].id = cudaLaunchAttributeProgrammaticStreamSerialization;
        attrs[0].val.programmaticStreamSerializationAllowed = 1;
        cfg.attrs = attrs;
        cfg.numAttrs = 1;
        cudaLaunchKernelEx(&cfg, reduce_fin_kernel, bpp, lamda, out);
    }
}

// round 11
// speedup vs baseline: 1.0032x; 1.0032x over previous
#include <cuda_runtime.h>
#include <cstdint>

// Problem shape (fixed by the reference setup_inputs)
#define B_SZ   4
#define N_PTS  8192
#define M_PTS  8192

// Chamfer compute tiling (R5 config: best measured)
#define BLOCK  128                 // threads per block (4 warps)
#define OWN    8                   // owner pred points per thread
#define TI     (BLOCK * OWN)       // 1024 pred points per block
#define TILE   256                 // target points per block (one shared tile)
#define TILE2  (TILE / 2)          // packed j-pairs
#define IC     (N_PTS / TI)        // 8  i-chunks
#define JC     (M_PTS / TILE)      // 32 j-chunks
#define TOTAL  (IC * JC * B_SZ)    // 1024 blocks (single wave at 7/SM on 148 SMs)
#define RWORK  256                 // last-finishing blocks that do the reduction
#define NPTS_T (B_SZ * N_PTS)      // 32768 (== B_SZ * M_PTS)

#define FINF __int_as_float(0x7f800000)

typedef unsigned long long ull;

// Complement-encoded global min arrays. v = 0.5*d^2 >= 0 always, so
// enc(v) = ~bits(v) is monotone DECREASING in v => max(enc) == min(v),
// identity 0 (zero-init / reset state). atomicMax with unused return => REDG.
__device__ unsigned gEncX[NPTS_T];   // min_j 0.5*d^2 per pred point (encoded)
__device__ unsigned gEncY[NPTS_T];   // min_i 0.5*d^2 per target point (encoded)
__device__ float gSumX;
__device__ float gSumY;
__device__ int   gDone;   // phase-1 completion ticket
__device__ int   gRed;    // phase-2 completion ticket

__device__ __forceinline__ unsigned encMin(float v) { return ~__float_as_uint(v); }
__device__ __forceinline__ float    decMin(unsigned e) { return __uint_as_float(~e); }

// ---- packed f32x2 helpers ----
__device__ __forceinline__ ull pack2(float lo, float hi) {
    ull r;
    asm("mov.b64 %0, {%1,%2};" : "=l"(r) : "f"(lo), "f"(hi));
    return r;
}
__device__ __forceinline__ ull fma2(ull a, ull b, ull c) {
    ull d;
    asm("fma.rn.f32x2 %0, %1, %2, %3;" : "=l"(d) : "l"(a), "l"(b), "l"(c));
    return d;
}
__device__ __forceinline__ ull add2(ull a, ull b) {
    ull d;
    asm("add.rn.f32x2 %0, %1, %2;" : "=l"(d) : "l"(a), "l"(b));
    return d;
}
__device__ __forceinline__ void unpack2(ull v, float& lo, float& hi) {
    asm("mov.b64 {%0,%1}, %2;" : "=f"(lo), "=f"(hi) : "l"(v));
}

// Single fused kernel.
// Phase 1: each unique pair (i,j) once as v = 0.5*d^2(i,j) (R5 inner loop).
//   Prologue stages all global reads through LDG.128 -> shared (low MLP_p1
//   to minimize cross-CTA L1tex-queue wave spread), then distributes via LDS.
//   Row mins -> registers -> REDG encoded fold. Col mins -> per-warp shared
//   (lane-rotated, race-free) -> REDG encoded fold.
// Phase 2 (last RWORK finishers): spin till all folds visible, then one
//   point/thread: decode min, reset, block-sum, finalize. No second launch.
__global__ __launch_bounds__(BLOCK, 7) void chamfer_fused_kernel(
    const float* __restrict__ pred, const float* __restrict__ target,
    const float* __restrict__ bpp, const float* __restrict__ lamda,
    float* __restrict__ out)
{
    // Pair-packed SoA target tile: element k holds coords of {j=2k, j=2k+1}.
    __shared__ ull sTx[TILE2], sTy[TILE2], sTz[TILE2], sTw[TILE2];
    __shared__ ull sCol[BLOCK / 32][TILE2];   // per-warp packed column mins
    __shared__ float sStage[TI * 3];           // 12KB staging (owners, then tile)
    __shared__ int sTicket;
    __shared__ float sx[BLOCK / 32], sy[BLOCK / 32];

    const int b = blockIdx.z;
    const float* __restrict__ predB = pred   + (size_t)b * N_PTS * 3;
    const float* __restrict__ targB = target + (size_t)b * M_PTS * 3;

    const int ic = blockIdx.x;
    const int jc = blockIdx.y;
    const int Ibase = ic * TI;
    const int Jbase = jc * TILE;
    const int t = threadIdx.x;
    const int lane = t & 31;
    const int w = t >> 5;

    // init per-warp colmins to +inf
    ull inf2 = pack2(FINF, FINF);
#pragma unroll
    for (int k = t; k < (BLOCK / 32) * TILE2; k += BLOCK)
        ((ull*)sCol)[k] = inf2;

    // ---- stage owner points: 768 float4 coalesced (6 LDG.128 per thread) ----
    {
        const float4* __restrict__ src4 = (const float4*)(predB + 3 * Ibase);
        float4* st4 = (float4*)sStage;
#pragma unroll
        for (int k = t; k < (TI * 3) / 4; k += BLOCK)
            st4[k] = src4[k];
    }
    __syncthreads();

    // owner pred points from shared (word-stride 3 => conflict-free):
    // negated coords + half-norm, duplicated into f32x2 pairs
    ull ax[OWN], ay[OWN], az[OWN], hp[OWN];
    float rm[OWN];
#pragma unroll
    for (int p = 0; p < OWN; p++) {
        int base = 3 * (t + p * BLOCK);
        float x = sStage[base + 0], y = sStage[base + 1], z = sStage[base + 2];
        float h = 0.5f * (x * x + y * y + z * z);
        ax[p] = pack2(-x, -x); ay[p] = pack2(-y, -y); az[p] = pack2(-z, -z);
        hp[p] = pack2(h, h);
        rm[p] = FINF;
    }
    __syncthreads();   // all owner reads done before staging buffer reuse

    // ---- stage target tile: 192 float4 coalesced (2 LDG.128 per thread) ----
    {
        const float4* __restrict__ src4 = (const float4*)(targB + 3 * Jbase);
        float4* st4 = (float4*)sStage;
#pragma unroll
        for (int k = t; k < (TILE * 3) / 4; k += BLOCK)
            st4[k] = src4[k];
    }
    __syncthreads();

    // build pair-packed SoA tile (x, y, z, 0.5|t|^2) from staged data
    for (int k = t; k < TILE; k += BLOCK) {
        float x = sStage[3 * k + 0], y = sStage[3 * k + 1], z = sStage[3 * k + 2];
        ((float*)sTx)[k] = x;
        ((float*)sTy)[k] = y;
        ((float*)sTz)[k] = z;
        ((float*)sTw)[k] = 0.5f * (x * x + y * y + z * z);
    }
    __syncthreads();

    ull* scol = sCol[w];

    for (int s = 0; s < TILE2; s++) {
        int jp = (s + lane) & (TILE2 - 1);   // lane-exclusive within warp each step
        ull tx = sTx[jp], ty = sTy[jp], tz = sTz[jp], tw = sTw[jp];
        float c0 = FINF, c1 = FINF;
#pragma unroll
        for (int p = 0; p < OWN; p++) {
            ull v = fma2(az[p], tz, add2(tw, hp[p]));  // 0.5(|p|^2+|t|^2) - pz*tz
            v = fma2(ay[p], ty, v);
            v = fma2(ax[p], tx, v);                     // = 0.5 * d^2  (>= 0)
            float v0, v1;
            unpack2(v, v0, v1);
            rm[p] = fminf(rm[p], fminf(v0, v1));        // row min (over j)
            c0 = fminf(c0, v0);                          // col partial
            c1 = fminf(c1, v1);
        }
        // fold into per-warp column min (lane-exclusive jp, no race)
        ull cc = scol[jp];
        float o0, o1;
        unpack2(cc, o0, o1);
        scol[jp] = pack2(fminf(o0, c0), fminf(o1, c1));
    }

    // row mins -> global encoded fold (return unused => REDG)
#pragma unroll
    for (int p = 0; p < OWN; p++)
        atomicMax(&gEncX[b * N_PTS + Ibase + t + p * BLOCK], encMin(rm[p]));

    __syncthreads();

    // column mins: combine 4 warps' arrays, one jp per thread (BLOCK == TILE2)
    {
        int jp = t;
        float m0 = FINF, m1 = FINF;
#pragma unroll
        for (int w2 = 0; w2 < BLOCK / 32; w2++) {
            float a, bb;
            unpack2(sCol[w2][jp], a, bb);
            m0 = fminf(m0, a);
            m1 = fminf(m1, bb);
        }
        atomicMax(&gEncY[b * M_PTS + Jbase + 2 * jp + 0], encMin(m0));
        atomicMax(&gEncY[b * M_PTS + Jbase + 2 * jp + 1], encMin(m1));
    }

    // ---- phase-2 gate: completion ticket ----
    __threadfence();   // all REDs of this block visible before the ticket
    if (t == 0) sTicket = atomicAdd(&gDone, 1);
    __syncthreads();
    const int ticket = sTicket;
    if (ticket < TOTAL - RWORK) return;   // early finishers exit

    // last RWORK finishers: wait for all folds (deadlock-safe: single wave,
    // launch_bounds pins 7 blocks/SM => 1036 slots >= 1024 blocks)
    if (t == 0) {
        while (*(volatile int*)&gDone < TOTAL) __nanosleep(64);
    }
    __syncthreads();
    __threadfence();   // order our reads after the observed completion

    // phase 2: one point per thread (RWORK*BLOCK == NPTS_T)
    const int rb = ticket - (TOTAL - RWORK);   // 0..RWORK-1
    const int i  = rb * BLOCK + t;

    float vx = 2.0f * decMin(gEncX[i]);   // d^2 = 2 * (0.5 d^2)
    float vy = 2.0f * decMin(gEncY[i]);

    // reset for the next graph replay (identity of encoded max is 0)
    gEncX[i] = 0u;
    gEncY[i] = 0u;

#pragma unroll
    for (int off = 16; off > 0; off >>= 1) {
        vx += __shfl_down_sync(0xffffffffu, vx, off);
        vy += __shfl_down_sync(0xffffffffu, vy, off);
    }
    if (lane == 0) { sx[w] = vx; sy[w] = vy; }
    __syncthreads();
    if (w == 0) {
        vx = (lane < (BLOCK >> 5)) ? sx[lane] : 0.0f;
        vy = (lane < (BLOCK >> 5)) ? sy[lane] : 0.0f;
#pragma unroll
        for (int off = 2; off > 0; off >>= 1) {
            vx += __shfl_down_sync(0xffffffffu, vx, off);
            vy += __shfl_down_sync(0xffffffffu, vy, off);
        }
        if (lane == 0) {
            atomicAdd(&gSumX, vx);
            atomicAdd(&gSumY, vy);
            __threadfence();
            int rt = atomicAdd(&gRed, 1);
            if (rt == RWORK - 1) {
                float sX = atomicAdd(&gSumX, 0.0f);   // all prior adds visible
                float sY = atomicAdd(&gSumY, 0.0f);
                float dist = sX * (1.0f / (B_SZ * N_PTS)) + sY * (1.0f / (B_SZ * M_PTS));
                out[0] = dist + lamda[0] * bpp[0];
                // reset for the next graph replay
                gSumX = 0.0f;
                gSumY = 0.0f;
                gDone = 0;
                __threadfence();
                gRed = 0;
            }
        }
    }
}

extern "C" void kernel_launch(void* const* d_in, const int* in_sizes, int n_in,
                              void* d_out, int out_size)
{
    const float* pred   = (const float*)d_in[0];
    const float* target = (const float*)d_in[1];
    const float* bpp    = (const float*)d_in[2];
    const float* lamda  = (const float*)d_in[3];
    float* out = (float*)d_out;

    // Single fused launch: staged-load chamfer + REDG min fold +
    // ticket-gated reduction + finalize
    dim3 grid(IC, JC, B_SZ);   // (8, 32, 4) = 1024 blocks, single wave
    chamfer_fused_kernel<<<grid, BLOCK>>>(pred, target, bpp, lamda, out);
}

// round 12
// speedup vs baseline: 1.0336x; 1.0303x over previous
#include <cuda_runtime.h>
#include <cstdint>

// Problem shape (fixed by the reference setup_inputs)
#define B_SZ   4
#define N_PTS  8192
#define M_PTS  8192

// Chamfer compute tiling: half-size j-tiles, ~2 waves for spread smoothing
#define BLOCK  128                 // threads per block (4 warps)
#define OWN    8                   // owner pred points per thread
#define TI     (BLOCK * OWN)       // 1024 pred points per block
#define TILE   128                 // target points per block (half of R5)
#define TILE2  (TILE / 2)          // 64 packed j-pairs
#define IC     (N_PTS / TI)        // 8  i-chunks
#define JC     (M_PTS / TILE)      // 64 j-chunks
#define TOTAL  (IC * JC * B_SZ)    // 2048 blocks (~2 waves at 7/SM)
#define RWORK  256                 // last-finishing blocks do the reduction
#define NPTS_T (B_SZ * N_PTS)      // 32768 (== B_SZ * M_PTS, == RWORK*BLOCK)

#define FINF __int_as_float(0x7f800000)

typedef unsigned long long ull;

// Complement-encoded global min arrays. v = 0.5*d^2 >= 0 always, so
// enc(v) = ~bits(v) is monotone DECREASING in v => max(enc) == min(v),
// identity 0 (zero-init / reset state). atomicMax with unused return => REDG.
__device__ unsigned gEncX[NPTS_T];   // min_j 0.5*d^2 per pred point (encoded)
__device__ unsigned gEncY[NPTS_T];   // min_i 0.5*d^2 per target point (encoded)
__device__ float gSumX;
__device__ float gSumY;
__device__ int   gDone;   // phase-1 completion ticket
__device__ int   gRed;    // phase-2 completion ticket

__device__ __forceinline__ unsigned encMin(float v) { return ~__float_as_uint(v); }
__device__ __forceinline__ float    decMin(unsigned e) { return __uint_as_float(~e); }

// ---- packed f32x2 helpers ----
__device__ __forceinline__ ull pack2(float lo, float hi) {
    ull r;
    asm("mov.b64 %0, {%1,%2};" : "=l"(r) : "f"(lo), "f"(hi));
    return r;
}
__device__ __forceinline__ ull fma2(ull a, ull b, ull c) {
    ull d;
    asm("fma.rn.f32x2 %0, %1, %2, %3;" : "=l"(d) : "l"(a), "l"(b), "l"(c));
    return d;
}
__device__ __forceinline__ ull add2(ull a, ull b) {
    ull d;
    asm("add.rn.f32x2 %0, %1, %2;" : "=l"(d) : "l"(a), "l"(b));
    return d;
}
__device__ __forceinline__ void unpack2(ull v, float& lo, float& hi) {
    asm("mov.b64 {%0,%1}, %2;" : "=f"(lo), "=f"(hi) : "l"(v));
}

// Single fused kernel.
// Phase 1 (2048 blocks, ~2 waves): each unique pair (i,j) once as
//   v = 0.5*d^2(i,j) = (0.5|t|^2 + 0.5|p|^2) - p.t   [1 add2 + 3 fma2, 2 j's]
//   Row mins -> registers -> REDG encoded fold.
//   Col mins -> per-warp shared (lane-rotated, race-free) -> REDG fold.
// Phase 2 (last RWORK finishers): spin till all folds visible, then one
//   point/thread: decode min, reset, block-sum, finalize. No second launch.
__global__ __launch_bounds__(BLOCK, 7) void chamfer_fused_kernel(
    const float* __restrict__ pred, const float* __restrict__ target,
    const float* __restrict__ bpp, const float* __restrict__ lamda,
    float* __restrict__ out)
{
    // Pair-packed SoA target tile: element k holds coords of {j=2k, j=2k+1}.
    __shared__ ull sTx[TILE2], sTy[TILE2], sTz[TILE2], sTw[TILE2];
    __shared__ ull sCol[BLOCK / 32][TILE2];   // per-warp packed column mins
    __shared__ int sTicket;
    __shared__ float sx[BLOCK / 32], sy[BLOCK / 32];

    const int b = blockIdx.z;
    const float* __restrict__ predB = pred   + (size_t)b * N_PTS * 3;
    const float* __restrict__ targB = target + (size_t)b * M_PTS * 3;

    const int ic = blockIdx.x;
    const int jc = blockIdx.y;
    const int Ibase = ic * TI;
    const int Jbase = jc * TILE;
    const int t = threadIdx.x;
    const int lane = t & 31;
    const int w = t >> 5;

    // init per-warp colmins to +inf
    ull inf2 = pack2(FINF, FINF);
#pragma unroll
    for (int k = t; k < (BLOCK / 32) * TILE2; k += BLOCK)
        ((ull*)sCol)[k] = inf2;

    // load target tile (x, y, z, 0.5|t|^2), pair-packed SoA (TILE <= BLOCK)
    if (t < TILE) {
        int j = Jbase + t;
        float x = targB[3 * j + 0], y = targB[3 * j + 1], z = targB[3 * j + 2];
        ((float*)sTx)[t] = x;
        ((float*)sTy)[t] = y;
        ((float*)sTz)[t] = z;
        ((float*)sTw)[t] = 0.5f * (x * x + y * y + z * z);
    }

    // owner pred points: negated coords + half-norm, duplicated into f32x2 pairs
    ull ax[OWN], ay[OWN], az[OWN], hp[OWN];
    float rm[OWN];
#pragma unroll
    for (int p = 0; p < OWN; p++) {
        int i = Ibase + t + p * BLOCK;
        float x = predB[3 * i + 0], y = predB[3 * i + 1], z = predB[3 * i + 2];
        float h = 0.5f * (x * x + y * y + z * z);
        ax[p] = pack2(-x, -x); ay[p] = pack2(-y, -y); az[p] = pack2(-z, -z);
        hp[p] = pack2(h, h);
        rm[p] = FINF;
    }

    __syncthreads();

    ull* scol = sCol[w];

    for (int s = 0; s < TILE2; s++) {
        int jp = (s + lane) & (TILE2 - 1);   // lane-exclusive within warp each step
        ull tx = sTx[jp], ty = sTy[jp], tz = sTz[jp], tw = sTw[jp];
        float c0 = FINF, c1 = FINF;
#pragma unroll
        for (int p = 0; p < OWN; p++) {
            ull v = fma2(az[p], tz, add2(tw, hp[p]));  // 0.5(|p|^2+|t|^2) - pz*tz
            v = fma2(ay[p], ty, v);
            v = fma2(ax[p], tx, v);                     // = 0.5 * d^2  (>= 0)
            float v0, v1;
            unpack2(v, v0, v1);
            rm[p] = fminf(rm[p], fminf(v0, v1));        // row min (over j)
            c0 = fminf(c0, v0);                          // col partial
            c1 = fminf(c1, v1);
        }
        // fold into per-warp column min (lane-exclusive jp, no race)
        ull cc = scol[jp];
        float o0, o1;
        unpack2(cc, o0, o1);
        scol[jp] = pack2(fminf(o0, c0), fminf(o1, c1));
    }

    // row mins -> global encoded fold (return unused => REDG)
#pragma unroll
    for (int p = 0; p < OWN; p++)
        atomicMax(&gEncX[b * N_PTS + Ibase + t + p * BLOCK], encMin(rm[p]));

    __syncthreads();

    // column mins: combine 4 warps' arrays (threads 0..TILE2-1, one jp each)
    if (t < TILE2) {
        int jp = t;
        float m0 = FINF, m1 = FINF;
#pragma unroll
        for (int w2 = 0; w2 < BLOCK / 32; w2++) {
            float a, bb;
            unpack2(sCol[w2][jp], a, bb);
            m0 = fminf(m0, a);
            m1 = fminf(m1, bb);
        }
        atomicMax(&gEncY[b * M_PTS + Jbase + 2 * jp + 0], encMin(m0));
        atomicMax(&gEncY[b * M_PTS + Jbase + 2 * jp + 1], encMin(m1));
    }

    // ---- phase-2 gate: completion ticket ----
    __threadfence();   // all REDs of this block visible before the ticket
    if (t == 0) sTicket = atomicAdd(&gDone, 1);
    __syncthreads();
    const int ticket = sTicket;
    if (ticket < TOTAL - RWORK) return;   // early finishers exit

    // last RWORK finishers: wait for all folds. Deadlock-free: spinners
    // (<=256) << resident capacity (1036 at 7/SM); unstarted blocks always
    // find freed slots since early finishers exit.
    if (t == 0) {
        while (*(volatile int*)&gDone < TOTAL) __nanosleep(64);
    }
    __syncthreads();
    __threadfence();   // order our reads after the observed completion

    // phase 2: one point per thread (RWORK*BLOCK == NPTS_T)
    const int rb = ticket - (TOTAL - RWORK);   // 0..RWORK-1
    const int i  = rb * BLOCK + t;

    float vx = 2.0f * decMin(gEncX[i]);   // d^2 = 2 * (0.5 d^2)
    float vy = 2.0f * decMin(gEncY[i]);

    // reset for the next graph replay (identity of encoded max is 0)
    gEncX[i] = 0u;
    gEncY[i] = 0u;

#pragma unroll
    for (int off = 16; off > 0; off >>= 1) {
        vx += __shfl_down_sync(0xffffffffu, vx, off);
        vy += __shfl_down_sync(0xffffffffu, vy, off);
    }
    if (lane == 0) { sx[w] = vx; sy[w] = vy; }
    __syncthreads();
    if (w == 0) {
        vx = (lane < (BLOCK >> 5)) ? sx[lane] : 0.0f;
        vy = (lane < (BLOCK >> 5)) ? sy[lane] : 0.0f;
#pragma unroll
        for (int off = 2; off > 0; off >>= 1) {
            vx += __shfl_down_sync(0xffffffffu, vx, off);
            vy += __shfl_down_sync(0xffffffffu, vy, off);
        }
        if (lane == 0) {
            atomicAdd(&gSumX, vx);
            atomicAdd(&gSumY, vy);
            __threadfence();
            int rt = atomicAdd(&gRed, 1);
            if (rt == RWORK - 1) {
                float sX = atomicAdd(&gSumX, 0.0f);   // all prior adds visible
                float sY = atomicAdd(&gSumY, 0.0f);
                float dist = sX * (1.0f / (B_SZ * N_PTS)) + sY * (1.0f / (B_SZ * M_PTS));
                out[0] = dist + lamda[0] * bpp[0];
                // reset for the next graph replay
                gSumX = 0.0f;
                gSumY = 0.0f;
                gDone = 0;
                __threadfence();
                gRed = 0;
            }
        }
    }
}

extern "C" void kernel_launch(void* const* d_in, const int* in_sizes, int n_in,
                              void* d_out, int out_size)
{
    const float* pred   = (const float*)d_in[0];
    const float* target = (const float*)d_in[1];
    const float* bpp    = (const float*)d_in[2];
    const float* lamda  = (const float*)d_in[3];
    float* out = (float*)d_out;

    // Single fused launch: 2-wave chamfer (spread smoothing) + REDG min fold
    // + ticket-gated reduction + finalize
    dim3 grid(IC, JC, B_SZ);   // (8, 64, 4) = 2048 blocks
    chamfer_fused_kernel<<<grid, BLOCK>>>(pred, target, bpp, lamda, out);
}